// round 10
// baseline (speedup 1.0000x reference)
#include <cuda_runtime.h>

#define S_DIM 100000
#define G_DIM 18000
#define H_DIM 256
#define E_DIM 600000
#define B_DIM 256

#define G4_DIM  4500   // G_DIM/4 float4 columns
#define KT2     8      // k-tiles (32 k's each)
#define GSTRIPS 141    // ceil(4500/32) g4-strips
#define CHUNKS  50     // gemv chunks along S
#define ROWS    8      // gemv rows per block
#define SCAT_BLOCKS 586   // ceil(150000/256)
#define C0_BLOCKS   9     // const0 tail blocks

// INVARIANT: g_v == 0 at every kernel_launch entry (statically zero at load;
// k_gemv re-zeroes it on exit when v is dead). k_build_v's grid.y==KT2 slice
// zeroes coef/out/const0 before their writers run.
__device__ float g_v[G_DIM];
__device__ float g_coef[S_DIM];
__device__ float g_const0;

// ---------------------------------------------------------------------------
// Kernel 1: grid=(GSTRIPS, KT2+1), block=256 = (tx:32 g-cols, ty:8 k-rows).
//   y <  KT2 : strip of 32 float4 g-columns x 32 k's. Each thread: 4
//              independent LDG.128 (TLP-driven MLP), smem tree-reduce over ty,
//              row ty==0 does 4 spread atomics per column (8 collisions/addr).
//   y == KT2 : zero coef + out + const0.
__global__ void __launch_bounds__(256)
k_build_v(const float* __restrict__ W1, const float* __restrict__ W2,
          float* __restrict__ out) {
    if (blockIdx.y == KT2) {
        float4 z = make_float4(0.f, 0.f, 0.f, 0.f);
        float4* c4 = reinterpret_cast<float4*>(g_coef);
        int i = blockIdx.x * 256 + threadIdx.x;          // 36096 threads / 25000 f4
        if (i < S_DIM / 4) c4[i] = z;
        if (blockIdx.x == 0) {
            out[threadIdx.x] = 0.0f;                     // 256 threads == B_DIM
            if (threadIdx.x == 0) g_const0 = 0.0f;
        }
        return;
    }
    const int tx = threadIdx.x & 31;
    const int ty = threadIdx.x >> 5;
    const int g4 = blockIdx.x * 32 + tx;                 // 0..4511
    const int k0 = blockIdx.y * 32;

    __shared__ float w2s[32];
    if (threadIdx.x < 32) w2s[threadIdx.x] = W2[k0 + threadIdx.x];
    __syncthreads();

    const float4* __restrict__ W14 = reinterpret_cast<const float4*>(W1);
    float4 acc = make_float4(0.f, 0.f, 0.f, 0.f);
    if (g4 < G4_DIM) {
        #pragma unroll
        for (int j = 0; j < 4; j++) {
            int k = k0 + ty + j * 8;
            float4 w = __ldg(&W14[(size_t)k * G4_DIM + g4]);
            float s = w2s[ty + j * 8];
            acc.x = fmaf(w.x, s, acc.x);
            acc.y = fmaf(w.y, s, acc.y);
            acc.z = fmaf(w.z, s, acc.z);
            acc.w = fmaf(w.w, s, acc.w);
        }
    }

    __shared__ float4 red[8][32];
    red[ty][tx] = acc;
    __syncthreads();
    if (ty < 4) {
        float4 o = red[ty + 4][tx];
        acc.x += o.x; acc.y += o.y; acc.z += o.z; acc.w += o.w;
        red[ty][tx] = acc;
    }
    __syncthreads();
    if (ty < 2) {
        float4 o = red[ty + 2][tx];
        acc.x += o.x; acc.y += o.y; acc.z += o.z; acc.w += o.w;
        red[ty][tx] = acc;
    }
    __syncthreads();
    if (ty == 0 && g4 < G4_DIM) {
        float4 o = red[1][tx];
        acc.x += o.x; acc.y += o.y; acc.z += o.z; acc.w += o.w;
        float* vo = &g_v[g4 * 4];
        atomicAdd(vo + 0, acc.x);
        atomicAdd(vo + 1, acc.y);
        atomicAdd(vo + 2, acc.z);
        atomicAdd(vo + 3, acc.w);
    }
}

// ---------------------------------------------------------------------------
// Kernel 2: edge scatter (4 edges/thread, vectorized) + const0 tail blocks.
__global__ void k_scatter(const int* __restrict__ snp, const int* __restrict__ gidx,
                          const float* __restrict__ ew,
                          const float* __restrict__ gene_bias,
                          const float* __restrict__ b1, const float* __restrict__ W2,
                          const float* __restrict__ b2) {
    if (blockIdx.x < SCAT_BLOCKS) {
        int i4 = blockIdx.x * blockDim.x + threadIdx.x;     // quad index
        if (i4 >= E_DIM / 4) return;
        int4   s4 = reinterpret_cast<const int4*>(snp)[i4];
        int4   g4 = reinterpret_cast<const int4*>(gidx)[i4];
        float4 w4 = reinterpret_cast<const float4*>(ew)[i4];
        float v0 = g_v[g4.x], v1 = g_v[g4.y], v2 = g_v[g4.z], v3 = g_v[g4.w];
        atomicAdd(&g_coef[s4.x], w4.x * v0);
        atomicAdd(&g_coef[s4.y], w4.y * v1);
        atomicAdd(&g_coef[s4.z], w4.z * v2);
        atomicAdd(&g_coef[s4.w], w4.w * v3);
        return;
    }
    // ---- const0 tail ----
    int local = blockIdx.x - SCAT_BLOCKS;                   // 0..8
    int start = local * (G_DIM / C0_BLOCKS);                // 2000 per block
    float acc = 0.0f;
    for (int g = start + threadIdx.x; g < start + G_DIM / C0_BLOCKS; g += blockDim.x)
        acc = fmaf(g_v[g], gene_bias[g], acc);
    if (local == 0) {
        acc = fmaf(W2[threadIdx.x], b1[threadIdx.x], acc);  // blockDim == H_DIM
        if (threadIdx.x == 0) acc += b2[0];
    }
    __shared__ float sm[32];
    int lane = threadIdx.x & 31, wid = threadIdx.x >> 5;
    #pragma unroll
    for (int o = 16; o > 0; o >>= 1) acc += __shfl_down_sync(0xffffffffu, acc, o);
    if (lane == 0) sm[wid] = acc;
    __syncthreads();
    if (wid == 0) {
        acc = (lane < (blockDim.x >> 5)) ? sm[lane] : 0.0f;
        #pragma unroll
        for (int o = 16; o > 0; o >>= 1) acc += __shfl_down_sync(0xffffffffu, acc, o);
        if (lane == 0) atomicAdd(&g_const0, acc);
    }
}

// ---------------------------------------------------------------------------
// Kernel 3: GEMV (proven config, ~5.2 TB/s measured ceiling for this pattern).
// grid=(CHUNKS, B/ROWS)=(50,32)=1600. Epilogue: blockIdx.x==0 blocks re-zero
// g_v (dead here) to restore the entry invariant for the next launch.
__global__ void __launch_bounds__(256, 6)
k_gemv(const float* __restrict__ x, float* __restrict__ out) {
    const int per  = (S_DIM / 4) / CHUNKS;         // 500
    const int base = blockIdx.x * per;
    const int r0   = blockIdx.y * ROWS;
    const float4* __restrict__ cf = reinterpret_cast<const float4*>(g_coef);

    float acc[ROWS];
    #pragma unroll
    for (int j = 0; j < ROWS; j++) acc[j] = 0.0f;

    #pragma unroll
    for (int it = 0; it < 2; it++) {
        int off = it * 256 + threadIdx.x;
        if (off < per) {
            int i = base + off;
            float4 cv = __ldg(&cf[i]);
            #pragma unroll
            for (int j = 0; j < ROWS; j++) {
                float4 xv = __ldcs(reinterpret_cast<const float4*>(
                                x + (size_t)(r0 + j) * S_DIM) + i);
                acc[j] += xv.x * cv.x + xv.y * cv.y + xv.z * cv.z + xv.w * cv.w;
            }
        }
    }

    __shared__ float sm[ROWS][8];
    int lane = threadIdx.x & 31, wid = threadIdx.x >> 5;
    #pragma unroll
    for (int j = 0; j < ROWS; j++) {
        float v = acc[j];
        #pragma unroll
        for (int o = 16; o > 0; o >>= 1) v += __shfl_down_sync(0xffffffffu, v, o);
        if (lane == 0) sm[j][wid] = v;
    }
    __syncthreads();
    if (threadIdx.x < ROWS * 8) {
        int j = threadIdx.x >> 3, w = threadIdx.x & 7;
        float v = sm[j][w];
        #pragma unroll
        for (int o = 4; o > 0; o >>= 1) v += __shfl_down_sync(0xffffffffu, v, o);
        if (w == 0) {
            if (blockIdx.x == 0) v += g_const0;    // exactly one chunk adds const0
            atomicAdd(&out[r0 + j], v);
        }
    }

    // ---- epilogue: restore g_v == 0 for the next kernel_launch call ----
    if (blockIdx.x == 0) {
        int i = blockIdx.y * 256 + threadIdx.x;    // 8192 threads over 18000
        #pragma unroll
        for (int rep = 0; rep < 3; rep++, i += 8192)
            if (i < G_DIM) g_v[i] = 0.0f;
    }
}

// ---------------------------------------------------------------------------
extern "C" void kernel_launch(void* const* d_in, const int* in_sizes, int n_in,
                              void* d_out, int out_size) {
    const float* x    = (const float*)d_in[0];
    const int*   snp  = (const int*)  d_in[1];
    const int*   gidx = (const int*)  d_in[2];
    const float* ew   = (const float*)d_in[3];
    const float* gb   = (const float*)d_in[4];
    const float* W1   = (const float*)d_in[5];
    const float* b1   = (const float*)d_in[6];
    const float* W2   = (const float*)d_in[7];
    const float* b2   = (const float*)d_in[8];
    float* out = (float*)d_out;

    k_build_v<<<dim3(GSTRIPS, KT2 + 1), 256>>>(W1, W2, out);
    k_scatter<<<SCAT_BLOCKS + C0_BLOCKS, 256>>>(snp, gidx, ew, gb, b1, W2, b2);
    k_gemv<<<dim3(CHUNKS, B_DIM / ROWS), 256>>>(x, out);
}